// round 14
// baseline (speedup 1.0000x reference)
#include <cuda_runtime.h>
#include <cuda_fp16.h>
#include <cstdint>
#include <math.h>

#define B_   4
#define SQ_  1024
#define SKV_ 1024
#define M_   8
#define D_   64
#define H_   8
#define F_   64
#define BH_  (B_*H_)

// ---------------- scratch (device globals; no allocation) ----------------
__device__ float  g_Wqf[H_*D_*F_];
__device__ float  g_Wkf[H_*D_*F_];
__device__ __half g_qrff[(size_t)BH_*SQ_*2*F_];      // [bh][q][128]
__device__ __half g_krff[(size_t)BH_*SKV_*2*F_];     // [bh][k][128]
__device__ __half g_vah [(size_t)B_*SKV_*M_*D_];     // v_atoms in half (row-major)
__device__ __half g_Wvh [512*64];
__device__ __half g_Woh [64*512];
__device__ __half g_va  [(size_t)BH_*SKV_*512];      // [bh][s][m*64+e]
__device__ __half g_outh[(size_t)BH_*SQ_*M_*D_];     // [(b,q,m)][(h,e)] half

__device__ __forceinline__ uint32_t s2u(const void* p) {
    uint32_t a;
    asm("{ .reg .u64 t; cvta.to.shared.u64 t, %1; cvt.u32.u64 %0, t; }" : "=r"(a) : "l"(p));
    return a;
}

// ---------------- K0: convert v_atoms / Wv / Wo to half ----------------
__global__ __launch_bounds__(256) void k_cvt(const float* __restrict__ va,
                                             const float* __restrict__ Wv,
                                             const float* __restrict__ Wo) {
    int i = blockIdx.x*256 + threadIdx.x;          // grid 2048 -> i < 524288
    float4 v = *(const float4*)&va[(size_t)i*4];
    __half2 h0 = __floats2half2_rn(v.x, v.y), h1 = __floats2half2_rn(v.z, v.w);
    uint2 pk; pk.x = *(uint32_t*)&h0; pk.y = *(uint32_t*)&h1;
    *(uint2*)&g_vah[(size_t)i*4] = pk;
    if (i < 8192) {
        float4 a = *(const float4*)&Wv[i*4];
        __half2 a0 = __floats2half2_rn(a.x, a.y), a1 = __floats2half2_rn(a.z, a.w);
        uint2 p2; p2.x = *(uint32_t*)&a0; p2.y = *(uint32_t*)&a1;
        *(uint2*)&g_Wvh[i*4] = p2;
        float4 b = *(const float4*)&Wo[i*4];
        __half2 b0 = __floats2half2_rn(b.x, b.y), b1 = __floats2half2_rn(b.z, b.w);
        uint2 p3; p3.x = *(uint32_t*)&b0; p3.y = *(uint32_t*)&b1;
        *(uint2*)&g_Woh[i*4] = p3;
    }
}

// ---------------- K1: combined projection-RFF matrices ----------------
__global__ __launch_bounds__(256) void k_combine(const float* __restrict__ Wq,
                                                 const float* __restrict__ Wk,
                                                 const float* __restrict__ base,
                                                 const float* __restrict__ log_bw) {
    __shared__ float sWq[64*64], sWk[64*64], sB[64*64];
    int h = blockIdx.x;
    float inv = expf(-log_bw[h]);
    for (int i = threadIdx.x; i < 4096; i += 256) {
        sWq[i] = Wq[h*4096 + i];
        sWk[i] = Wk[h*4096 + i];
        sB[i]  = base[h*4096 + i] * inv;
    }
    __syncthreads();
    for (int idx = threadIdx.x; idx < 4096; idx += 256) {
        int d = idx >> 6, f = idx & 63;
        float aq = 0.f, ak = 0.f;
        #pragma unroll
        for (int e = 0; e < 64; e++) {
            float bf = sB[e*64 + f];
            aq = fmaf(sWq[e*64 + d], bf, aq);
            ak = fmaf(sWk[e*64 + d], bf, ak);
        }
        g_Wqf[h*4096 + d*64 + f] = aq;
        g_Wkf[h*4096 + d*64 + f] = ak;
    }
}

// ---------------- K2: fused projection + RFF encode, f-blocked x2 ----------
__global__ __launch_bounds__(256) void k_rff(const float* __restrict__ atoms,
                                             const float* __restrict__ weights,
                                             int is_q) {
    __shared__ float sWT[64*68];                    // [f][d], pad 68
    __shared__ __align__(16) float sAt[8][8][64];   // [sl][m][d]
    __shared__ float sw[8][8];
    int bh = blockIdx.y;
    int b = bh >> 3, h = bh & 7;
    const float* Wf = is_q ? g_Wqf : g_Wkf;
    __half* dstbase = (is_q ? g_qrff : g_krff);
    for (int i = threadIdx.x; i < 4096; i += 256) {
        int d = i >> 6, f = i & 63;
        sWT[f*68 + d] = Wf[h*4096 + i];
    }
    int s0 = blockIdx.x * 16;
    int fl = threadIdx.x & 31;
    int sl = threadIdx.x >> 5;
    for (int ss = 0; ss < 16; ss += 8) {
        __syncthreads();
        for (int i = threadIdx.x; i < 4096; i += 256) {
            int si = i >> 9;          // 0..7
            int md = i & 511;
            sAt[si][md >> 6][md & 63] =
                atoms[(size_t)(b*1024 + s0 + ss + si)*512 + md];
        }
        if (threadIdx.x < 64) {
            int si = threadIdx.x >> 3, m = threadIdx.x & 7;
            sw[si][m] = weights[(b*1024 + s0 + ss + si)*8 + m];
        }
        __syncthreads();
        float p0[8], p1[8];
        #pragma unroll
        for (int m = 0; m < 8; m++) { p0[m] = 0.f; p1[m] = 0.f; }
        #pragma unroll
        for (int dq = 0; dq < 64; dq += 4) {
            float4 w0 = *(const float4*)&sWT[fl*68 + dq];
            float4 w1 = *(const float4*)&sWT[(fl + 32)*68 + dq];
            #pragma unroll
            for (int m = 0; m < 8; m++) {
                float4 av = *(const float4*)&sAt[sl][m][dq];
                p0[m] = fmaf(av.x, w0.x, p0[m]);
                p0[m] = fmaf(av.y, w0.y, p0[m]);
                p0[m] = fmaf(av.z, w0.z, p0[m]);
                p0[m] = fmaf(av.w, w0.w, p0[m]);
                p1[m] = fmaf(av.x, w1.x, p1[m]);
                p1[m] = fmaf(av.y, w1.y, p1[m]);
                p1[m] = fmaf(av.z, w1.z, p1[m]);
                p1[m] = fmaf(av.w, w1.w, p1[m]);
            }
        }
        float ac0 = 0.f, as0 = 0.f, ac1 = 0.f, as1 = 0.f;
        #pragma unroll
        for (int m = 0; m < 8; m++) {
            float w = sw[sl][m];
            float sv, cv;
            __sincosf(p0[m], &sv, &cv);
            ac0 = fmaf(w, cv, ac0); as0 = fmaf(w, sv, as0);
            __sincosf(p1[m], &sv, &cv);
            ac1 = fmaf(w, cv, ac1); as1 = fmaf(w, sv, as1);
        }
        int s = s0 + ss + sl;
        __half* dst = dstbase + ((size_t)bh*1024 + s)*128;
        dst[fl]           = __float2half(ac0 * 0.125f);
        dst[fl + 32]      = __float2half(ac1 * 0.125f);
        dst[64 + fl]      = __float2half(as0 * 0.125f);
        dst[96 + fl]      = __float2half(as1 * 0.125f);
    }
}

// ---------------- K3: va projection via HMMA (M=32768, N=512, K=64) ----------
__global__ __launch_bounds__(256) void k_va2() {
    __shared__ __align__(16) char sraw[36864];
    __half (*sA)[72] = (__half (*)[72])sraw;                 // [128][72]
    __half (*sB)[72] = (__half (*)[72])(sraw + 18432);       // [128][72]
    __half (*so)[2][512] = (__half (*)[2][512])sraw;         // aliased staging

    int tid = threadIdx.x, wid = tid >> 5, lid = tid & 31;
    int cb = blockIdx.x * 128, rb = blockIdx.y * 128;
    int warp_m = (wid & 3) * 32, warp_n = (wid >> 2) * 64;

    #pragma unroll
    for (int i = 0; i < 4; i++) {
        int id = tid + i*256;
        int r = id >> 3, c = id & 7;
        uint32_t d = s2u(&sA[r][c*8]);
        asm volatile("cp.async.cg.shared.global [%0], [%1], 16;"
                     :: "r"(d), "l"(g_vah + (size_t)(rb + r)*64 + c*8));
    }
    #pragma unroll
    for (int i = 0; i < 4; i++) {
        int id = tid + i*256;
        int r = id >> 3, c = id & 7;
        uint32_t d = s2u(&sB[r][c*8]);
        asm volatile("cp.async.cg.shared.global [%0], [%1], 16;"
                     :: "r"(d), "l"(g_Wvh + (size_t)(cb + r)*64 + c*8));
    }
    asm volatile("cp.async.commit_group;" ::: "memory");
    asm volatile("cp.async.wait_group 0;" ::: "memory");
    __syncthreads();

    float acc[2][8][4] = {};
    #pragma unroll
    for (int kk = 0; kk < 4; kk++) {
        uint32_t af[2][4];
        #pragma unroll
        for (int mi = 0; mi < 2; mi++) {
            uint32_t addr = s2u(&sA[warp_m + mi*16 + (lid & 15)][kk*16 + ((lid >> 4) << 3)]);
            asm volatile("ldmatrix.sync.aligned.m8n8.x4.shared.b16 {%0,%1,%2,%3}, [%4];"
                : "=r"(af[mi][0]), "=r"(af[mi][1]), "=r"(af[mi][2]), "=r"(af[mi][3])
                : "r"(addr));
        }
        #pragma unroll
        for (int nj = 0; nj < 4; nj++) {
            uint32_t r0, r1, r2, r3;
            int n = warp_n + nj*16 + ((lid >> 4) << 3) + (lid & 7);
            int k = kk*16 + (((lid >> 3) & 1) << 3);
            uint32_t addr = s2u(&sB[n][k]);
            asm volatile("ldmatrix.sync.aligned.m8n8.x4.shared.b16 {%0,%1,%2,%3}, [%4];"
                : "=r"(r0), "=r"(r1), "=r"(r2), "=r"(r3) : "r"(addr));
            #pragma unroll
            for (int mi = 0; mi < 2; mi++) {
                asm volatile("mma.sync.aligned.m16n8k16.row.col.f32.f16.f16.f32 "
                    "{%0,%1,%2,%3}, {%4,%5,%6,%7}, {%8,%9}, {%0,%1,%2,%3};"
                    : "+f"(acc[mi][nj*2][0]), "+f"(acc[mi][nj*2][1]),
                      "+f"(acc[mi][nj*2][2]), "+f"(acc[mi][nj*2][3])
                    : "r"(af[mi][0]), "r"(af[mi][1]), "r"(af[mi][2]), "r"(af[mi][3]),
                      "r"(r0), "r"(r1));
                asm volatile("mma.sync.aligned.m16n8k16.row.col.f32.f16.f16.f32 "
                    "{%0,%1,%2,%3}, {%4,%5,%6,%7}, {%8,%9}, {%0,%1,%2,%3};"
                    : "+f"(acc[mi][nj*2+1][0]), "+f"(acc[mi][nj*2+1][1]),
                      "+f"(acc[mi][nj*2+1][2]), "+f"(acc[mi][nj*2+1][3])
                    : "r"(af[mi][0]), "r"(af[mi][1]), "r"(af[mi][2]), "r"(af[mi][3]),
                      "r"(r2), "r"(r3));
            }
        }
    }
    __syncthreads();   // inputs dead; reuse arena as output staging
    #pragma unroll
    for (int mi = 0; mi < 2; mi++)
        #pragma unroll
        for (int ni = 0; ni < 8; ni++) {
            int col = warp_n + ni*8 + (lid & 3)*2;
            int h_l = col >> 6, e = col & 63;
            int rl0 = warp_m + mi*16 + (lid >> 2);
            *(__half2*)&so[rl0 >> 3][h_l][(rl0 & 7)*64 + e] =
                __floats2half2_rn(acc[mi][ni][0], acc[mi][ni][1]);
            int rl1 = rl0 + 8;
            *(__half2*)&so[rl1 >> 3][h_l][(rl1 & 7)*64 + e] =
                __floats2half2_rn(acc[mi][ni][2], acc[mi][ni][3]);
        }
    __syncthreads();
    int b = rb >> 13, s0 = (rb >> 3) & 1023;
    int h0 = cb >> 6;
    #pragma unroll
    for (int i = 0; i < 8; i++) {
        int idx = tid + i*256;
        int row = idx >> 6, c = idx & 63;
        int s_l = row >> 1, h_l = row & 1;
        *(uint4*)&g_va[((size_t)((b*8 + h0 + h_l)*1024) + s0 + s_l)*512 + c*8] =
            *(const uint4*)&so[s_l][h_l][c*8];
    }
}

// ---------------- K4: fused flash attention, seq-tile 64, 2 CTAs/SM ----------
// smem: q [128][136] + k [2][64][136] + v [2][64][136] = 102KB
#define FLASH_SMEM 104448
#define TSTR 136
#define KSTG 8704     // halves per kv stage (64*136)
__global__ __launch_bounds__(256, 2) void k_flash(const float* __restrict__ log_temp) {
    extern __shared__ __align__(16) __half fsm[];
    __half* qs = fsm;                     // [128][136]
    __half* ks = fsm + 17408;             // [2][64][136]
    __half* vs = fsm + 17408 + 2*KSTG;    // [2][64][136]

    int tid = threadIdx.x, wid = tid >> 5, lid = tid & 31;
    int bh = blockIdx.z, b = bh >> 3, h = bh & 7;
    int qb = blockIdx.y * 128, nb = blockIdx.x * 128;
    const __half* Qg = g_qrff + ((size_t)bh*1024 + qb)*128;
    const __half* Kg = g_krff + (size_t)bh*1024*128;
    const __half* Vg = g_va   + (size_t)bh*1024*512 + nb;
    float temp = __expf(log_temp[h]);

    auto loadQ = [&]() {
        #pragma unroll
        for (int i = 0; i < 8; i++) {
            int id = tid + i*256;
            int r = id >> 4, c = id & 15;
            uint32_t d = s2u(qs + r*TSTR + c*8);
            asm volatile("cp.async.cg.shared.global [%0], [%1], 16;"
                         :: "r"(d), "l"(Qg + (size_t)r*128 + c*8));
        }
    };
    auto loadKV = [&](int st, int kt) {   // kt in units of 64 seq rows
        __half* kp = ks + st*KSTG;
        __half* vp = vs + st*KSTG;
        #pragma unroll
        for (int i = 0; i < 4; i++) {
            int id = tid + i*256;          // 0..1023
            int r = id >> 4, c = id & 15;
            uint32_t d = s2u(kp + r*TSTR + c*8);
            asm volatile("cp.async.cg.shared.global [%0], [%1], 16;"
                         :: "r"(d), "l"(Kg + (size_t)(kt*64 + r)*128 + c*8));
        }
        #pragma unroll
        for (int i = 0; i < 4; i++) {
            int id = tid + i*256;
            int r = id >> 4, c = id & 15;
            uint32_t d = s2u(vp + r*TSTR + c*8);
            asm volatile("cp.async.cg.shared.global [%0], [%1], 16;"
                         :: "r"(d), "l"(Vg + (size_t)(kt*64 + r)*512 + c*8));
        }
        asm volatile("cp.async.commit_group;" ::: "memory");
    };

    loadQ(); loadKV(0, 0);
    loadKV(1, 1);

    float accO[16][4] = {};
    float m0 = -1e30f, m1 = -1e30f, l0 = 0.f, l1 = 0.f;

    for (int kt = 0; kt < 16; kt++) {
        int st = kt & 1;
        if (kt < 15) asm volatile("cp.async.wait_group 1;" ::: "memory");
        else         asm volatile("cp.async.wait_group 0;" ::: "memory");
        __syncthreads();

        // ---- S = q @ k^T (16q x 64seq per warp) ----
        float accS[8][4] = {};
        const __half* kp = ks + st*KSTG;
        #pragma unroll
        for (int kk = 0; kk < 8; kk++) {      // feature dim 128
            uint32_t af[4];
            {
                uint32_t addr = s2u(qs + (wid*16 + (lid & 15))*TSTR + kk*16 + ((lid >> 4) << 3));
                asm volatile("ldmatrix.sync.aligned.m8n8.x4.shared.b16 {%0,%1,%2,%3}, [%4];"
                    : "=r"(af[0]), "=r"(af[1]), "=r"(af[2]), "=r"(af[3]) : "r"(addr));
            }
            #pragma unroll
            for (int nj = 0; nj < 4; nj++) {  // seq dim 64
                uint32_t r0, r1, r2, r3;
                int n = nj*16 + ((lid >> 4) << 3) + (lid & 7);
                int k = kk*16 + (((lid >> 3) & 1) << 3);
                uint32_t addr = s2u(kp + n*TSTR + k);
                asm volatile("ldmatrix.sync.aligned.m8n8.x4.shared.b16 {%0,%1,%2,%3}, [%4];"
                    : "=r"(r0), "=r"(r1), "=r"(r2), "=r"(r3) : "r"(addr));
                asm volatile("mma.sync.aligned.m16n8k16.row.col.f32.f16.f16.f32 "
                    "{%0,%1,%2,%3}, {%4,%5,%6,%7}, {%8,%9}, {%0,%1,%2,%3};"
                    : "+f"(accS[nj*2][0]), "+f"(accS[nj*2][1]),
                      "+f"(accS[nj*2][2]), "+f"(accS[nj*2][3])
                    : "r"(af[0]), "r"(af[1]), "r"(af[2]), "r"(af[3]), "r"(r0), "r"(r1));
                asm volatile("mma.sync.aligned.m16n8k16.row.col.f32.f16.f16.f32 "
                    "{%0,%1,%2,%3}, {%4,%5,%6,%7}, {%8,%9}, {%0,%1,%2,%3};"
                    : "+f"(accS[nj*2+1][0]), "+f"(accS[nj*2+1][1]),
                      "+f"(accS[nj*2+1][2]), "+f"(accS[nj*2+1][3])
                    : "r"(af[0]), "r"(af[1]), "r"(af[2]), "r"(af[3]), "r"(r2), "r"(r3));
            }
        }

        // ---- online softmax ----
        float mx0 = -1e30f, mx1 = -1e30f;
        #pragma unroll
        for (int ni = 0; ni < 8; ni++) {
            accS[ni][0] *= temp; accS[ni][1] *= temp;
            accS[ni][2] *= temp; accS[ni][3] *= temp;
            mx0 = fmaxf(mx0, fmaxf(accS[ni][0], accS[ni][1]));
            mx1 = fmaxf(mx1, fmaxf(accS[ni][2], accS[ni][3]));
        }
        mx0 = fmaxf(mx0, __shfl_xor_sync(~0u, mx0, 1));
        mx0 = fmaxf(mx0, __shfl_xor_sync(~0u, mx0, 2));
        mx1 = fmaxf(mx1, __shfl_xor_sync(~0u, mx1, 1));
        mx1 = fmaxf(mx1, __shfl_xor_sync(~0u, mx1, 2));
        float mn0 = fmaxf(m0, mx0), mn1 = fmaxf(m1, mx1);
        float sf0 = __expf(m0 - mn0), sf1 = __expf(m1 - mn1);
        m0 = mn0; m1 = mn1;
        float s0 = 0.f, s1 = 0.f;
        uint32_t pf[8][2];
        #pragma unroll
        for (int ni = 0; ni < 8; ni++) {
            float p0 = __expf(accS[ni][0] - m0);
            float p1 = __expf(accS[ni][1] - m0);
            float p2 = __expf(accS[ni][2] - m1);
            float p3 = __expf(accS[ni][3] - m1);
            s0 += p0 + p1; s1 += p2 + p3;
            __half2 h01 = __floats2half2_rn(p0, p1);
            __half2 h23 = __floats2half2_rn(p2, p3);
            pf[ni][0] = *(uint32_t*)&h01;
            pf[ni][1] = *(uint32_t*)&h23;
        }
        s0 += __shfl_xor_sync(~0u, s0, 1); s0 += __shfl_xor_sync(~0u, s0, 2);
        s1 += __shfl_xor_sync(~0u, s1, 1); s1 += __shfl_xor_sync(~0u, s1, 2);
        l0 = l0*sf0 + s0; l1 = l1*sf1 + s1;
        #pragma unroll
        for (int n2 = 0; n2 < 16; n2++) {
            accO[n2][0] *= sf0; accO[n2][1] *= sf0;
            accO[n2][2] *= sf1; accO[n2][3] *= sf1;
        }

        // ---- O += P @ V (seq 64 = 4 k-steps of 16) ----
        const __half* vp = vs + st*KSTG;
        #pragma unroll
        for (int kk2 = 0; kk2 < 4; kk2++) {
            uint32_t a0 = pf[kk2*2][0],   a1 = pf[kk2*2][1];
            uint32_t a2 = pf[kk2*2+1][0], a3 = pf[kk2*2+1][1];
            #pragma unroll
            for (int n2p = 0; n2p < 8; n2p++) {
                uint32_t r0, r1, r2, r3;
                int krow = kk2*16 + (lid & 7) + (((lid >> 3) & 1) << 3);
                int ncol = n2p*16 + ((lid >> 4) << 3);
                uint32_t addr = s2u(vp + krow*TSTR + ncol);
                asm volatile("ldmatrix.sync.aligned.m8n8.x4.trans.shared.b16 {%0,%1,%2,%3}, [%4];"
                    : "=r"(r0), "=r"(r1), "=r"(r2), "=r"(r3) : "r"(addr));
                asm volatile("mma.sync.aligned.m16n8k16.row.col.f32.f16.f16.f32 "
                    "{%0,%1,%2,%3}, {%4,%5,%6,%7}, {%8,%9}, {%0,%1,%2,%3};"
                    : "+f"(accO[n2p*2][0]), "+f"(accO[n2p*2][1]),
                      "+f"(accO[n2p*2][2]), "+f"(accO[n2p*2][3])
                    : "r"(a0), "r"(a1), "r"(a2), "r"(a3), "r"(r0), "r"(r1));
                asm volatile("mma.sync.aligned.m16n8k16.row.col.f32.f16.f16.f32 "
                    "{%0,%1,%2,%3}, {%4,%5,%6,%7}, {%8,%9}, {%0,%1,%2,%3};"
                    : "+f"(accO[n2p*2+1][0]), "+f"(accO[n2p*2+1][1]),
                      "+f"(accO[n2p*2+1][2]), "+f"(accO[n2p*2+1][3])
                    : "r"(a0), "r"(a1), "r"(a2), "r"(a3), "r"(r2), "r"(r3));
            }
        }
        __syncthreads();
        if (kt + 2 < 16) loadKV(st, kt + 2);
    }

    // epilogue: normalize + write HALF in oproj layout [(b,q,m)][(h,e)]
    float inv0 = 1.0f / l0, inv1 = 1.0f / l1;
    int q0 = qb + wid*16 + (lid >> 2);
    int q1 = q0 + 8;
    #pragma unroll
    for (int n2 = 0; n2 < 16; n2++) {
        int col = nb + n2*8 + (lid & 3)*2;
        int m = col >> 6, e = col & 63;
        __half* p0 = g_outh + ((size_t)(b*1024 + q0)*8 + m)*512 + h*64 + e;
        __half* p1 = g_outh + ((size_t)(b*1024 + q1)*8 + m)*512 + h*64 + e;
        *(__half2*)p0 = __floats2half2_rn(accO[n2][0]*inv0, accO[n2][1]*inv0);
        *(__half2*)p1 = __floats2half2_rn(accO[n2][2]*inv1, accO[n2][3]*inv1);
    }
}

// ---------------- K7: output projection via HMMA (M=32768, N=64, K=512) -----
__global__ __launch_bounds__(256) void k_oproj2(float* __restrict__ out_atoms) {
    __shared__ __align__(16) __half sA[2][128][40];
    __shared__ __align__(16) __half sB[2][64][40];
    int tid = threadIdx.x, wid = tid >> 5, lid = tid & 31;
    int rb = blockIdx.x * 128;
    int warp_m = (wid & 3) * 32, warp_n = (wid >> 2) * 32;
    float acc[2][4][4] = {};

    auto load = [&](int st, int kc) {
        #pragma unroll
        for (int i = 0; i < 2; i++) {
            int id = tid + i*256;
            int r = id >> 2, c = id & 3;
            uint32_t d = s2u(&sA[st][r][c*8]);
            asm volatile("cp.async.cg.shared.global [%0], [%1], 16;"
                         :: "r"(d), "l"(g_outh + (size_t)(rb + r)*512 + kc + c*8));
        }
        {
            int r = tid >> 2, c = tid & 3;
            uint32_t d = s2u(&sB[st][r][c*8]);
            asm volatile("cp.async.cg.shared.global [%0], [%1], 16;"
                         :: "r"(d), "l"(g_Woh + (size_t)r*512 + kc + c*8));
        }
        asm volatile("cp.async.commit_group;" ::: "memory");
    };

    load(0, 0);
    load(1, 32);

    for (int c = 0; c < 16; c++) {
        int st = c & 1;
        if (c < 14) asm volatile("cp.async.wait_group 1;" ::: "memory");
        else        asm volatile("cp.async.wait_group 0;" ::: "memory");
        __syncthreads();

        #pragma unroll
        for (int kk = 0; kk < 32; kk += 16) {
            uint32_t af[2][4];
            #pragma unroll
            for (int mi = 0; mi < 2; mi++) {
                uint32_t addr = s2u(&sA[st][warp_m + mi*16 + (lid & 15)][kk + ((lid >> 4) << 3)]);
                asm volatile("ldmatrix.sync.aligned.m8n8.x4.shared.b16 {%0,%1,%2,%3}, [%4];"
                    : "=r"(af[mi][0]), "=r"(af[mi][1]), "=r"(af[mi][2]), "=r"(af[mi][3])
                    : "r"(addr));
            }
            #pragma unroll
            for (int nj = 0; nj < 2; nj++) {
                uint32_t r0, r1, r2, r3;
                int n = warp_n + nj*16 + ((lid >> 4) << 3) + (lid & 7);
                int k = kk + (((lid >> 3) & 1) << 3);
                uint32_t addr = s2u(&sB[st][n][k]);
                asm volatile("ldmatrix.sync.aligned.m8n8.x4.shared.b16 {%0,%1,%2,%3}, [%4];"
                    : "=r"(r0), "=r"(r1), "=r"(r2), "=r"(r3) : "r"(addr));
                #pragma unroll
                for (int mi = 0; mi < 2; mi++) {
                    asm volatile("mma.sync.aligned.m16n8k16.row.col.f32.f16.f16.f32 "
                        "{%0,%1,%2,%3}, {%4,%5,%6,%7}, {%8,%9}, {%0,%1,%2,%3};"
                        : "+f"(acc[mi][nj*2][0]), "+f"(acc[mi][nj*2][1]),
                          "+f"(acc[mi][nj*2][2]), "+f"(acc[mi][nj*2][3])
                        : "r"(af[mi][0]), "r"(af[mi][1]), "r"(af[mi][2]), "r"(af[mi][3]),
                          "r"(r0), "r"(r1));
                    asm volatile("mma.sync.aligned.m16n8k16.row.col.f32.f16.f16.f32 "
                        "{%0,%1,%2,%3}, {%4,%5,%6,%7}, {%8,%9}, {%0,%1,%2,%3};"
                        : "+f"(acc[mi][nj*2+1][0]), "+f"(acc[mi][nj*2+1][1]),
                          "+f"(acc[mi][nj*2+1][2]), "+f"(acc[mi][nj*2+1][3])
                        : "r"(af[mi][0]), "r"(af[mi][1]), "r"(af[mi][2]), "r"(af[mi][3]),
                          "r"(r2), "r"(r3));
                }
            }
        }
        __syncthreads();
        if (c + 2 < 16) load(st, (c + 2)*32);
    }

    #pragma unroll
    for (int mi = 0; mi < 2; mi++)
        #pragma unroll
        for (int ni = 0; ni < 4; ni++) {
            int row = rb + warp_m + mi*16 + (lid >> 2);
            int col = warp_n + ni*8 + (lid & 3)*2;
            float* Cp = out_atoms + (size_t)row*64 + col;
            Cp[0]       = acc[mi][ni][0];
            Cp[1]       = acc[mi][ni][1];
            Cp[64*8]    = acc[mi][ni][2];
            Cp[64*8 + 1]= acc[mi][ni][3];
        }
}

// ---------------- K8: log-weight update ----------------
__global__ __launch_bounds__(64) void k_lw(const float* __restrict__ Ww,
                                           const float* __restrict__ qlw,
                                           const float* __restrict__ out_atoms,
                                           float* __restrict__ out2) {
    __shared__ float mean[64];
    int bq = blockIdx.x;
    int t = threadIdx.x;
    float s = 0.f;
    #pragma unroll
    for (int m = 0; m < 8; m++)
        s += out_atoms[(size_t)(bq*8 + m)*64 + t];
    mean[t] = s * 0.125f;
    __syncthreads();
    if (t < 8) {
        float acc = 0.f;
        #pragma unroll
        for (int d = 0; d < 64; d++)
            acc = fmaf(mean[d], Ww[t*64 + d], acc);
        out2[bq*8 + t] = qlw[bq*8 + t] + acc;
    }
}

// ---------------- launch ----------------
extern "C" void kernel_launch(void* const* d_in, const int* in_sizes, int n_in,
                              void* d_out, int out_size) {
    const float* q_atoms   = (const float*)d_in[0];
    const float* q_weights = (const float*)d_in[1];
    const float* q_logw    = (const float*)d_in[2];
    const float* k_atoms   = (const float*)d_in[3];
    const float* k_weights = (const float*)d_in[4];
    const float* v_atoms   = (const float*)d_in[5];
    const float* Wq        = (const float*)d_in[6];
    const float* Wk        = (const float*)d_in[7];
    const float* Wv        = (const float*)d_in[8];
    const float* Wo        = (const float*)d_in[9];
    const float* Ww        = (const float*)d_in[10];
    const float* log_bw    = (const float*)d_in[11];
    const float* log_temp  = (const float*)d_in[12];
    const float* rff_base  = (const float*)d_in[13];

    float* out_atoms = (float*)d_out;
    float* out_lw    = (float*)d_out + (size_t)B_*SQ_*M_*D_;

    cudaFuncSetAttribute(k_flash, cudaFuncAttributeMaxDynamicSharedMemorySize, FLASH_SMEM);

    k_combine<<<H_, 256>>>(Wq, Wk, rff_base, log_bw);
    k_cvt<<<2048, 256>>>(v_atoms, Wv, Wo);
    k_rff<<<dim3(SQ_/16,  BH_), 256>>>(q_atoms, q_weights, 1);
    k_rff<<<dim3(SKV_/16, BH_), 256>>>(k_atoms, k_weights, 0);
    k_va2<<<dim3(4, 256), 256>>>();
    k_flash<<<dim3(4, 8, BH_), 256, FLASH_SMEM>>>(log_temp);
    k_oproj2<<<256, 256>>>(out_atoms);
    k_lw<<<B_*SQ_, 64>>>(Ww, q_logw, out_atoms, out_lw);
}

// round 16
// speedup vs baseline: 1.0410x; 1.0410x over previous
#include <cuda_runtime.h>
#include <cuda_fp16.h>
#include <cstdint>
#include <math.h>

#define B_   4
#define SQ_  1024
#define SKV_ 1024
#define M_   8
#define D_   64
#define H_   8
#define F_   64
#define BH_  (B_*H_)

// ---------------- scratch (device globals; no allocation) ----------------
__device__ float  g_Wqf[H_*D_*F_];
__device__ float  g_Wkf[H_*D_*F_];
__device__ __half g_qrff[(size_t)BH_*SQ_*2*F_];      // [bh][q][128]  (temp-scaled)
__device__ __half g_krff[(size_t)BH_*SKV_*2*F_];     // [bh][k][128]
__device__ __half g_vah [(size_t)B_*SKV_*M_*D_];
__device__ __half g_Wvh [512*64];
__device__ __half g_Woh [64*512];
__device__ __half g_va  [(size_t)BH_*SKV_*512];      // [bh][s][m*64+e]
__device__ __half g_outh[(size_t)BH_*SQ_*M_*D_];     // [(b,q,m)][(h,e)] half

__device__ __forceinline__ uint32_t s2u(const void* p) {
    uint32_t a;
    asm("{ .reg .u64 t; cvta.to.shared.u64 t, %1; cvt.u32.u64 %0, t; }" : "=r"(a) : "l"(p));
    return a;
}

// ---------------- K0: convert v_atoms / Wv / Wo to half ----------------
__global__ __launch_bounds__(256) void k_cvt(const float* __restrict__ va,
                                             const float* __restrict__ Wv,
                                             const float* __restrict__ Wo) {
    int i = blockIdx.x*256 + threadIdx.x;
    float4 v = *(const float4*)&va[(size_t)i*4];
    __half2 h0 = __floats2half2_rn(v.x, v.y), h1 = __floats2half2_rn(v.z, v.w);
    uint2 pk; pk.x = *(uint32_t*)&h0; pk.y = *(uint32_t*)&h1;
    *(uint2*)&g_vah[(size_t)i*4] = pk;
    if (i < 8192) {
        float4 a = *(const float4*)&Wv[i*4];
        __half2 a0 = __floats2half2_rn(a.x, a.y), a1 = __floats2half2_rn(a.z, a.w);
        uint2 p2; p2.x = *(uint32_t*)&a0; p2.y = *(uint32_t*)&a1;
        *(uint2*)&g_Wvh[i*4] = p2;
        float4 b = *(const float4*)&Wo[i*4];
        __half2 b0 = __floats2half2_rn(b.x, b.y), b1 = __floats2half2_rn(b.z, b.w);
        uint2 p3; p3.x = *(uint32_t*)&b0; p3.y = *(uint32_t*)&b1;
        *(uint2*)&g_Woh[i*4] = p3;
    }
}

// ---------------- K1: combined projection-RFF matrices ----------------
__global__ __launch_bounds__(256) void k_combine(const float* __restrict__ Wq,
                                                 const float* __restrict__ Wk,
                                                 const float* __restrict__ base,
                                                 const float* __restrict__ log_bw) {
    __shared__ float sWq[64*64], sWk[64*64], sB[64*64];
    int h = blockIdx.x;
    float inv = expf(-log_bw[h]);
    for (int i = threadIdx.x; i < 4096; i += 256) {
        sWq[i] = Wq[h*4096 + i];
        sWk[i] = Wk[h*4096 + i];
        sB[i]  = base[h*4096 + i] * inv;
    }
    __syncthreads();
    for (int idx = threadIdx.x; idx < 4096; idx += 256) {
        int d = idx >> 6, f = idx & 63;
        float aq = 0.f, ak = 0.f;
        #pragma unroll
        for (int e = 0; e < 64; e++) {
            float bf = sB[e*64 + f];
            aq = fmaf(sWq[e*64 + d], bf, aq);
            ak = fmaf(sWk[e*64 + d], bf, ak);
        }
        g_Wqf[h*4096 + d*64 + f] = aq;
        g_Wkf[h*4096 + d*64 + f] = ak;
    }
}

// ---------------- K2: fused projection + RFF encode, f-blocked x2 ----------
// q path: outputs pre-scaled by temperature (softmax-invariant placement).
__global__ __launch_bounds__(256) void k_rff(const float* __restrict__ atoms,
                                             const float* __restrict__ weights,
                                             const float* __restrict__ log_temp,
                                             int is_q) {
    __shared__ float sWT[64*68];
    __shared__ __align__(16) float sAt[8][8][64];
    __shared__ float sw[8][8];
    int bh = blockIdx.y;
    int b = bh >> 3, h = bh & 7;
    const float* Wf = is_q ? g_Wqf : g_Wkf;
    __half* dstbase = (is_q ? g_qrff : g_krff);
    float oscale = is_q ? (0.125f * __expf(log_temp[h])) : 0.125f;
    for (int i = threadIdx.x; i < 4096; i += 256) {
        int d = i >> 6, f = i & 63;
        sWT[f*68 + d] = Wf[h*4096 + i];
    }
    int s0 = blockIdx.x * 16;
    int fl = threadIdx.x & 31;
    int sl = threadIdx.x >> 5;
    for (int ss = 0; ss < 16; ss += 8) {
        __syncthreads();
        for (int i = threadIdx.x; i < 4096; i += 256) {
            int si = i >> 9;
            int md = i & 511;
            sAt[si][md >> 6][md & 63] =
                atoms[(size_t)(b*1024 + s0 + ss + si)*512 + md];
        }
        if (threadIdx.x < 64) {
            int si = threadIdx.x >> 3, m = threadIdx.x & 7;
            sw[si][m] = weights[(b*1024 + s0 + ss + si)*8 + m];
        }
        __syncthreads();
        float p0[8], p1[8];
        #pragma unroll
        for (int m = 0; m < 8; m++) { p0[m] = 0.f; p1[m] = 0.f; }
        #pragma unroll
        for (int dq = 0; dq < 64; dq += 4) {
            float4 w0 = *(const float4*)&sWT[fl*68 + dq];
            float4 w1 = *(const float4*)&sWT[(fl + 32)*68 + dq];
            #pragma unroll
            for (int m = 0; m < 8; m++) {
                float4 av = *(const float4*)&sAt[sl][m][dq];
                p0[m] = fmaf(av.x, w0.x, p0[m]);
                p0[m] = fmaf(av.y, w0.y, p0[m]);
                p0[m] = fmaf(av.z, w0.z, p0[m]);
                p0[m] = fmaf(av.w, w0.w, p0[m]);
                p1[m] = fmaf(av.x, w1.x, p1[m]);
                p1[m] = fmaf(av.y, w1.y, p1[m]);
                p1[m] = fmaf(av.z, w1.z, p1[m]);
                p1[m] = fmaf(av.w, w1.w, p1[m]);
            }
        }
        float ac0 = 0.f, as0 = 0.f, ac1 = 0.f, as1 = 0.f;
        #pragma unroll
        for (int m = 0; m < 8; m++) {
            float w = sw[sl][m];
            float sv, cv;
            __sincosf(p0[m], &sv, &cv);
            ac0 = fmaf(w, cv, ac0); as0 = fmaf(w, sv, as0);
            __sincosf(p1[m], &sv, &cv);
            ac1 = fmaf(w, cv, ac1); as1 = fmaf(w, sv, as1);
        }
        int s = s0 + ss + sl;
        __half* dst = dstbase + ((size_t)bh*1024 + s)*128;
        dst[fl]           = __float2half(ac0 * oscale);
        dst[fl + 32]      = __float2half(ac1 * oscale);
        dst[64 + fl]      = __float2half(as0 * oscale);
        dst[96 + fl]      = __float2half(as1 * oscale);
    }
}

// ---------------- K3: va projection via HMMA (M=32768, N=512, K=64) ----------
__global__ __launch_bounds__(256) void k_va2() {
    __shared__ __align__(16) char sraw[36864];
    __half (*sA)[72] = (__half (*)[72])sraw;
    __half (*sB)[72] = (__half (*)[72])(sraw + 18432);
    __half (*so)[2][512] = (__half (*)[2][512])sraw;     // aliased staging

    int tid = threadIdx.x, wid = tid >> 5, lid = tid & 31;
    int cb = blockIdx.x * 128, rb = blockIdx.y * 128;
    int warp_m = (wid & 3) * 32, warp_n = (wid >> 2) * 64;

    #pragma unroll
    for (int i = 0; i < 4; i++) {
        int id = tid + i*256;
        int r = id >> 3, c = id & 7;
        uint32_t d = s2u(&sA[r][c*8]);
        asm volatile("cp.async.cg.shared.global [%0], [%1], 16;"
                     :: "r"(d), "l"(g_vah + (size_t)(rb + r)*64 + c*8));
    }
    #pragma unroll
    for (int i = 0; i < 4; i++) {
        int id = tid + i*256;
        int r = id >> 3, c = id & 7;
        uint32_t d = s2u(&sB[r][c*8]);
        asm volatile("cp.async.cg.shared.global [%0], [%1], 16;"
                     :: "r"(d), "l"(g_Wvh + (size_t)(cb + r)*64 + c*8));
    }
    asm volatile("cp.async.commit_group;" ::: "memory");
    asm volatile("cp.async.wait_group 0;" ::: "memory");
    __syncthreads();

    float acc[2][8][4] = {};
    #pragma unroll
    for (int kk = 0; kk < 4; kk++) {
        uint32_t af[2][4];
        #pragma unroll
        for (int mi = 0; mi < 2; mi++) {
            uint32_t addr = s2u(&sA[warp_m + mi*16 + (lid & 15)][kk*16 + ((lid >> 4) << 3)]);
            asm volatile("ldmatrix.sync.aligned.m8n8.x4.shared.b16 {%0,%1,%2,%3}, [%4];"
                : "=r"(af[mi][0]), "=r"(af[mi][1]), "=r"(af[mi][2]), "=r"(af[mi][3])
                : "r"(addr));
        }
        #pragma unroll
        for (int nj = 0; nj < 4; nj++) {
            uint32_t r0, r1, r2, r3;
            int n = warp_n + nj*16 + ((lid >> 4) << 3) + (lid & 7);
            int k = kk*16 + (((lid >> 3) & 1) << 3);
            uint32_t addr = s2u(&sB[n][k]);
            asm volatile("ldmatrix.sync.aligned.m8n8.x4.shared.b16 {%0,%1,%2,%3}, [%4];"
                : "=r"(r0), "=r"(r1), "=r"(r2), "=r"(r3) : "r"(addr));
            #pragma unroll
            for (int mi = 0; mi < 2; mi++) {
                asm volatile("mma.sync.aligned.m16n8k16.row.col.f32.f16.f16.f32 "
                    "{%0,%1,%2,%3}, {%4,%5,%6,%7}, {%8,%9}, {%0,%1,%2,%3};"
                    : "+f"(acc[mi][nj*2][0]), "+f"(acc[mi][nj*2][1]),
                      "+f"(acc[mi][nj*2][2]), "+f"(acc[mi][nj*2][3])
                    : "r"(af[mi][0]), "r"(af[mi][1]), "r"(af[mi][2]), "r"(af[mi][3]),
                      "r"(r0), "r"(r1));
                asm volatile("mma.sync.aligned.m16n8k16.row.col.f32.f16.f16.f32 "
                    "{%0,%1,%2,%3}, {%4,%5,%6,%7}, {%8,%9}, {%0,%1,%2,%3};"
                    : "+f"(acc[mi][nj*2+1][0]), "+f"(acc[mi][nj*2+1][1]),
                      "+f"(acc[mi][nj*2+1][2]), "+f"(acc[mi][nj*2+1][3])
                    : "r"(af[mi][0]), "r"(af[mi][1]), "r"(af[mi][2]), "r"(af[mi][3]),
                      "r"(r2), "r"(r3));
            }
        }
    }
    __syncthreads();
    #pragma unroll
    for (int mi = 0; mi < 2; mi++)
        #pragma unroll
        for (int ni = 0; ni < 8; ni++) {
            int col = warp_n + ni*8 + (lid & 3)*2;
            int h_l = col >> 6, e = col & 63;
            int rl0 = warp_m + mi*16 + (lid >> 2);
            *(__half2*)&so[rl0 >> 3][h_l][(rl0 & 7)*64 + e] =
                __floats2half2_rn(acc[mi][ni][0], acc[mi][ni][1]);
            int rl1 = rl0 + 8;
            *(__half2*)&so[rl1 >> 3][h_l][(rl1 & 7)*64 + e] =
                __floats2half2_rn(acc[mi][ni][2], acc[mi][ni][3]);
        }
    __syncthreads();
    int b = rb >> 13, s0 = (rb >> 3) & 1023;
    int h0 = cb >> 6;
    #pragma unroll
    for (int i = 0; i < 8; i++) {
        int idx = tid + i*256;
        int row = idx >> 6, c = idx & 63;
        int s_l = row >> 1, h_l = row & 1;
        *(uint4*)&g_va[((size_t)((b*8 + h0 + h_l)*1024) + s0 + s_l)*512 + c*8] =
            *(const uint4*)&so[s_l][h_l][c*8];
    }
}

// ---------------- K4: fused flash attention (R13 config: q128, kv128x2) ------
#define FLASH_SMEM 174080
#define TSTR 136
__global__ __launch_bounds__(256) void k_flash() {
    extern __shared__ __align__(16) __half fsm[];
    __half* qs = fsm;
    __half* ks = fsm + 17408;
    __half* vs = fsm + 17408*3;

    int tid = threadIdx.x, wid = tid >> 5, lid = tid & 31;
    int bh = blockIdx.z, b = bh >> 3, h = bh & 7;
    int qb = blockIdx.y * 128, nb = blockIdx.x * 128;
    const __half* Qg = g_qrff + ((size_t)bh*1024 + qb)*128;
    const __half* Kg = g_krff + (size_t)bh*1024*128;
    const __half* Vg = g_va   + (size_t)bh*1024*512 + nb;

    auto loadQ = [&]() {
        #pragma unroll
        for (int i = 0; i < 8; i++) {
            int id = tid + i*256;
            int r = id >> 4, c = id & 15;
            uint32_t d = s2u(qs + r*TSTR + c*8);
            asm volatile("cp.async.cg.shared.global [%0], [%1], 16;"
                         :: "r"(d), "l"(Qg + (size_t)r*128 + c*8));
        }
    };
    auto loadKV = [&](int st, int kt) {
        __half* kp = ks + st*17408;
        __half* vp = vs + st*17408;
        #pragma unroll
        for (int i = 0; i < 8; i++) {
            int id = tid + i*256;
            int r = id >> 4, c = id & 15;
            uint32_t d = s2u(kp + r*TSTR + c*8);
            asm volatile("cp.async.cg.shared.global [%0], [%1], 16;"
                         :: "r"(d), "l"(Kg + (size_t)(kt*128 + r)*128 + c*8));
        }
        #pragma unroll
        for (int i = 0; i < 8; i++) {
            int id = tid + i*256;
            int r = id >> 4, c = id & 15;
            uint32_t d = s2u(vp + r*TSTR + c*8);
            asm volatile("cp.async.cg.shared.global [%0], [%1], 16;"
                         :: "r"(d), "l"(Vg + (size_t)(kt*128 + r)*512 + c*8));
        }
        asm volatile("cp.async.commit_group;" ::: "memory");
    };

    loadQ(); loadKV(0, 0);
    loadKV(1, 1);

    float accO[16][4] = {};
    float m0 = -1e30f, m1 = -1e30f, l0 = 0.f, l1 = 0.f;

    for (int kt = 0; kt < 8; kt++) {
        int st = kt & 1;
        if (kt < 7) asm volatile("cp.async.wait_group 1;" ::: "memory");
        else        asm volatile("cp.async.wait_group 0;" ::: "memory");
        __syncthreads();

        float accS[16][4] = {};
        const __half* kp = ks + st*17408;
        #pragma unroll
        for (int kk = 0; kk < 8; kk++) {
            uint32_t af[4];
            {
                uint32_t addr = s2u(qs + (wid*16 + (lid & 15))*TSTR + kk*16 + ((lid >> 4) << 3));
                asm volatile("ldmatrix.sync.aligned.m8n8.x4.shared.b16 {%0,%1,%2,%3}, [%4];"
                    : "=r"(af[0]), "=r"(af[1]), "=r"(af[2]), "=r"(af[3]) : "r"(addr));
            }
            #pragma unroll
            for (int nj = 0; nj < 8; nj++) {
                uint32_t r0, r1, r2, r3;
                int n = nj*16 + ((lid >> 4) << 3) + (lid & 7);
                int k = kk*16 + (((lid >> 3) & 1) << 3);
                uint32_t addr = s2u(kp + n*TSTR + k);
                asm volatile("ldmatrix.sync.aligned.m8n8.x4.shared.b16 {%0,%1,%2,%3}, [%4];"
                    : "=r"(r0), "=r"(r1), "=r"(r2), "=r"(r3) : "r"(addr));
                asm volatile("mma.sync.aligned.m16n8k16.row.col.f32.f16.f16.f32 "
                    "{%0,%1,%2,%3}, {%4,%5,%6,%7}, {%8,%9}, {%0,%1,%2,%3};"
                    : "+f"(accS[nj*2][0]), "+f"(accS[nj*2][1]),
                      "+f"(accS[nj*2][2]), "+f"(accS[nj*2][3])
                    : "r"(af[0]), "r"(af[1]), "r"(af[2]), "r"(af[3]), "r"(r0), "r"(r1));
                asm volatile("mma.sync.aligned.m16n8k16.row.col.f32.f16.f16.f32 "
                    "{%0,%1,%2,%3}, {%4,%5,%6,%7}, {%8,%9}, {%0,%1,%2,%3};"
                    : "+f"(accS[nj*2+1][0]), "+f"(accS[nj*2+1][1]),
                      "+f"(accS[nj*2+1][2]), "+f"(accS[nj*2+1][3])
                    : "r"(af[0]), "r"(af[1]), "r"(af[2]), "r"(af[3]), "r"(r2), "r"(r3));
            }
        }

        // online softmax (temp already folded into q)
        float mx0 = -1e30f, mx1 = -1e30f;
        #pragma unroll
        for (int ni = 0; ni < 16; ni++) {
            mx0 = fmaxf(mx0, fmaxf(accS[ni][0], accS[ni][1]));
            mx1 = fmaxf(mx1, fmaxf(accS[ni][2], accS[ni][3]));
        }
        mx0 = fmaxf(mx0, __shfl_xor_sync(~0u, mx0, 1));
        mx0 = fmaxf(mx0, __shfl_xor_sync(~0u, mx0, 2));
        mx1 = fmaxf(mx1, __shfl_xor_sync(~0u, mx1, 1));
        mx1 = fmaxf(mx1, __shfl_xor_sync(~0u, mx1, 2));
        float mn0 = fmaxf(m0, mx0), mn1 = fmaxf(m1, mx1);
        float sf0 = __expf(m0 - mn0), sf1 = __expf(m1 - mn1);
        m0 = mn0; m1 = mn1;
        float s0 = 0.f, s1 = 0.f;
        uint32_t pf[16][2];
        #pragma unroll
        for (int ni = 0; ni < 16; ni++) {
            float p0 = __expf(accS[ni][0] - m0);
            float p1 = __expf(accS[ni][1] - m0);
            float p2 = __expf(accS[ni][2] - m1);
            float p3 = __expf(accS[ni][3] - m1);
            s0 += p0 + p1; s1 += p2 + p3;
            __half2 h01 = __floats2half2_rn(p0, p1);
            __half2 h23 = __floats2half2_rn(p2, p3);
            pf[ni][0] = *(uint32_t*)&h01;
            pf[ni][1] = *(uint32_t*)&h23;
        }
        s0 += __shfl_xor_sync(~0u, s0, 1); s0 += __shfl_xor_sync(~0u, s0, 2);
        s1 += __shfl_xor_sync(~0u, s1, 1); s1 += __shfl_xor_sync(~0u, s1, 2);
        l0 = l0*sf0 + s0; l1 = l1*sf1 + s1;
        #pragma unroll
        for (int n2 = 0; n2 < 16; n2++) {
            accO[n2][0] *= sf0; accO[n2][1] *= sf0;
            accO[n2][2] *= sf1; accO[n2][3] *= sf1;
        }

        const __half* vp = vs + st*17408;
        #pragma unroll
        for (int kk2 = 0; kk2 < 8; kk2++) {
            uint32_t a0 = pf[kk2*2][0],   a1 = pf[kk2*2][1];
            uint32_t a2 = pf[kk2*2+1][0], a3 = pf[kk2*2+1][1];
            #pragma unroll
            for (int n2p = 0; n2p < 8; n2p++) {
                uint32_t r0, r1, r2, r3;
                int krow = kk2*16 + (lid & 7) + (((lid >> 3) & 1) << 3);
                int ncol = n2p*16 + ((lid >> 4) << 3);
                uint32_t addr = s2u(vp + krow*TSTR + ncol);
                asm volatile("ldmatrix.sync.aligned.m8n8.x4.trans.shared.b16 {%0,%1,%2,%3}, [%4];"
                    : "=r"(r0), "=r"(r1), "=r"(r2), "=r"(r3) : "r"(addr));
                asm volatile("mma.sync.aligned.m16n8k16.row.col.f32.f16.f16.f32 "
                    "{%0,%1,%2,%3}, {%4,%5,%6,%7}, {%8,%9}, {%0,%1,%2,%3};"
                    : "+f"(accO[n2p*2][0]), "+f"(accO[n2p*2][1]),
                      "+f"(accO[n2p*2][2]), "+f"(accO[n2p*2][3])
                    : "r"(a0), "r"(a1), "r"(a2), "r"(a3), "r"(r0), "r"(r1));
                asm volatile("mma.sync.aligned.m16n8k16.row.col.f32.f16.f16.f32 "
                    "{%0,%1,%2,%3}, {%4,%5,%6,%7}, {%8,%9}, {%0,%1,%2,%3};"
                    : "+f"(accO[n2p*2+1][0]), "+f"(accO[n2p*2+1][1]),
                      "+f"(accO[n2p*2+1][2]), "+f"(accO[n2p*2+1][3])
                    : "r"(a0), "r"(a1), "r"(a2), "r"(a3), "r"(r2), "r"(r3));
            }
        }
        __syncthreads();
        if (kt + 2 < 8) loadKV(st, kt + 2);
    }

    float inv0 = 1.0f / l0, inv1 = 1.0f / l1;
    int q0 = qb + wid*16 + (lid >> 2);
    int q1 = q0 + 8;
    #pragma unroll
    for (int n2 = 0; n2 < 16; n2++) {
        int col = nb + n2*8 + (lid & 3)*2;
        int m = col >> 6, e = col & 63;
        __half* p0 = g_outh + ((size_t)(b*1024 + q0)*8 + m)*512 + h*64 + e;
        __half* p1 = g_outh + ((size_t)(b*1024 + q1)*8 + m)*512 + h*64 + e;
        *(__half2*)p0 = __floats2half2_rn(accO[n2][0]*inv0, accO[n2][1]*inv0);
        *(__half2*)p1 = __floats2half2_rn(accO[n2][2]*inv1, accO[n2][3]*inv1);
    }
}

// ---------------- K7: output projection via HMMA + fused log-weight ---------
__global__ __launch_bounds__(256) void k_oproj2(const float* __restrict__ Ww,
                                                const float* __restrict__ qlw,
                                                float* __restrict__ out_atoms,
                                                float* __restrict__ out2) {
    __shared__ __align__(16) char arena[36864];
    __half (*sA)[40] = (__half (*)[40])arena;                 // [2*128][40]
    __half (*sB)[40] = (__half (*)[40])(arena + 20480);       // [2*64][40]
    float (*stage)[65] = (float (*)[65])arena;                // [128][65] aliased
    __shared__ float sMean[16][68];
    __shared__ float sWw[8][68];

    int tid = threadIdx.x, wid = tid >> 5, lid = tid & 31;
    int rb = blockIdx.x * 128;
    int warp_m = (wid & 3) * 32, warp_n = (wid >> 2) * 32;
    float acc[2][4][4] = {};

    for (int i = tid; i < 512; i += 256)
        sWw[i >> 6][i & 63] = Ww[i];

    auto load = [&](int st, int kc) {
        #pragma unroll
        for (int i = 0; i < 2; i++) {
            int id = tid + i*256;
            int r = id >> 2, c = id & 3;
            uint32_t d = s2u(&sA[st*128 + r][c*8]);
            asm volatile("cp.async.cg.shared.global [%0], [%1], 16;"
                         :: "r"(d), "l"(g_outh + (size_t)(rb + r)*512 + kc + c*8));
        }
        {
            int r = tid >> 2, c = tid & 3;
            uint32_t d = s2u(&sB[st*64 + r][c*8]);
            asm volatile("cp.async.cg.shared.global [%0], [%1], 16;"
                         :: "r"(d), "l"(g_Woh + (size_t)r*512 + kc + c*8));
        }
        asm volatile("cp.async.commit_group;" ::: "memory");
    };

    load(0, 0);
    load(1, 32);

    for (int c = 0; c < 16; c++) {
        int st = c & 1;
        if (c < 14) asm volatile("cp.async.wait_group 1;" ::: "memory");
        else        asm volatile("cp.async.wait_group 0;" ::: "memory");
        __syncthreads();

        #pragma unroll
        for (int kk = 0; kk < 32; kk += 16) {
            uint32_t af[2][4];
            #pragma unroll
            for (int mi = 0; mi < 2; mi++) {
                uint32_t addr = s2u(&sA[st*128 + warp_m + mi*16 + (lid & 15)][kk + ((lid >> 4) << 3)]);
                asm volatile("ldmatrix.sync.aligned.m8n8.x4.shared.b16 {%0,%1,%2,%3}, [%4];"
                    : "=r"(af[mi][0]), "=r"(af[mi][1]), "=r"(af[mi][2]), "=r"(af[mi][3])
                    : "r"(addr));
            }
            #pragma unroll
            for (int nj = 0; nj < 2; nj++) {
                uint32_t r0, r1, r2, r3;
                int n = warp_n + nj*16 + ((lid >> 4) << 3) + (lid & 7);
                int k = kk + (((lid >> 3) & 1) << 3);
                uint32_t addr = s2u(&sB[st*64 + n][k]);
                asm volatile("ldmatrix.sync.aligned.m8n8.x4.shared.b16 {%0,%1,%2,%3}, [%4];"
                    : "=r"(r0), "=r"(r1), "=r"(r2), "=r"(r3) : "r"(addr));
                #pragma unroll
                for (int mi = 0; mi < 2; mi++) {
                    asm volatile("mma.sync.aligned.m16n8k16.row.col.f32.f16.f16.f32 "
                        "{%0,%1,%2,%3}, {%4,%5,%6,%7}, {%8,%9}, {%0,%1,%2,%3};"
                        : "+f"(acc[mi][nj*2][0]), "+f"(acc[mi][nj*2][1]),
                          "+f"(acc[mi][nj*2][2]), "+f"(acc[mi][nj*2][3])
                        : "r"(af[mi][0]), "r"(af[mi][1]), "r"(af[mi][2]), "r"(af[mi][3]),
                          "r"(r0), "r"(r1));
                    asm volatile("mma.sync.aligned.m16n8k16.row.col.f32.f16.f16.f32 "
                        "{%0,%1,%2,%3}, {%4,%5,%6,%7}, {%8,%9}, {%0,%1,%2,%3};"
                        : "+f"(acc[mi][nj*2+1][0]), "+f"(acc[mi][nj*2+1][1]),
                          "+f"(acc[mi][nj*2+1][2]), "+f"(acc[mi][nj*2+1][3])
                        : "r"(af[mi][0]), "r"(af[mi][1]), "r"(af[mi][2]), "r"(af[mi][3]),
                          "r"(r2), "r"(r3));
                }
            }
        }
        __syncthreads();
        if (c + 2 < 16) load(st, (c + 2)*32);
    }
    // all reads of sA/sB done (post-loop sync above); stage aliases the arena
    #pragma unroll
    for (int mi = 0; mi < 2; mi++)
        #pragma unroll
        for (int ni = 0; ni < 4; ni++) {
            int row0 = warp_m + mi*16 + (lid >> 2);
            int col = warp_n + ni*8 + (lid & 3)*2;
            float* Cp = out_atoms + (size_t)(rb + row0)*64 + col;
            Cp[0]        = acc[mi][ni][0];
            Cp[1]        = acc[mi][ni][1];
            Cp[64*8]     = acc[mi][ni][2];
            Cp[64*8 + 1] = acc[mi][ni][3];
            stage[row0][col]     = acc[mi][ni][0];
            stage[row0][col + 1] = acc[mi][ni][1];
            stage[row0 + 8][col]     = acc[mi][ni][2];
            stage[row0 + 8][col + 1] = acc[mi][ni][3];
        }
    __syncthreads();
    // mean over m: 16 groups x 64 d
    #pragma unroll
    for (int i = 0; i < 4; i++) {
        int idx = tid + i*256;                // 0..1023
        int g = idx >> 6, d = idx & 63;
        float s = 0.f;
        #pragma unroll
        for (int m = 0; m < 8; m++) s += stage[g*8 + m][d];
        sMean[g][d] = s * 0.125f;
    }
    __syncthreads();
    if (tid < 128) {
        int g = tid >> 3, j = tid & 7;
        float a = 0.f;
        #pragma unroll
        for (int d = 0; d < 64; d++)
            a = fmaf(sMean[g][d], sWw[j][d], a);
        int gq = (rb >> 3) + g;               // global (b,q) index
        out2[gq*8 + j] = qlw[gq*8 + j] + a;
    }
}

// ---------------- launch ----------------
extern "C" void kernel_launch(void* const* d_in, const int* in_sizes, int n_in,
                              void* d_out, int out_size) {
    const float* q_atoms   = (const float*)d_in[0];
    const float* q_weights = (const float*)d_in[1];
    const float* q_logw    = (const float*)d_in[2];
    const float* k_atoms   = (const float*)d_in[3];
    const float* k_weights = (const float*)d_in[4];
    const float* v_atoms   = (const float*)d_in[5];
    const float* Wq        = (const float*)d_in[6];
    const float* Wk        = (const float*)d_in[7];
    const float* Wv        = (const float*)d_in[8];
    const float* Wo        = (const float*)d_in[9];
    const float* Ww        = (const float*)d_in[10];
    const float* log_bw    = (const float*)d_in[11];
    const float* log_temp  = (const float*)d_in[12];
    const float* rff_base  = (const float*)d_in[13];

    float* out_atoms = (float*)d_out;
    float* out_lw    = (float*)d_out + (size_t)B_*SQ_*M_*D_;

    cudaFuncSetAttribute(k_flash, cudaFuncAttributeMaxDynamicSharedMemorySize, FLASH_SMEM);

    k_combine<<<H_, 256>>>(Wq, Wk, rff_base, log_bw);
    k_cvt<<<2048, 256>>>(v_atoms, Wv, Wo);
    k_rff<<<dim3(SQ_/16,  BH_), 256>>>(q_atoms, q_weights, log_temp, 1);
    k_rff<<<dim3(SKV_/16, BH_), 256>>>(k_atoms, k_weights, log_temp, 0);
    k_va2<<<dim3(4, 256), 256>>>();
    k_flash<<<dim3(4, 8, BH_), 256, FLASH_SMEM>>>();
    k_oproj2<<<256, 256>>>(Ww, q_logw, out_atoms, out_lw);
}